// round 6
// baseline (speedup 1.0000x reference)
#include <cuda_runtime.h>
#include <cstdint>

#define FULL 0xffffffffu

constexpr int WPB = 4;   // warps per block

#define FMA_F32X2(out, a, b, c) \
    asm("fma.rn.f32x2 %0, %1, %2, %3;" : "=l"(out) : "l"(a), "l"(b), "l"(c))

__device__ __forceinline__ float warpSum(float v) {
    v += __shfl_xor_sync(FULL, v, 16);
    v += __shfl_xor_sync(FULL, v, 8);
    v += __shfl_xor_sync(FULL, v, 4);
    v += __shfl_xor_sync(FULL, v, 2);
    v += __shfl_xor_sync(FULL, v, 1);
    return v;
}
__device__ __forceinline__ float warpMin(float v) {
    #pragma unroll
    for (int o = 16; o > 0; o >>= 1) v = fminf(v, __shfl_xor_sync(FULL, v, o));
    return v;
}

// One warp per molecule.
// Phase 1: Gram C = G G^T, 16-feature chunks: own chunk in regs (16), peer rows
//          via broadcast LDS.128, packed f32x2 FMA. Row l of C lives in a[32].
// Phase 2: Householder tridiag, A register-resident, fully unrolled; sigma via
//          local 4-chain + 1 shfl; double-buffered V/W staging in shared.
// Phase 3: Sturm bisection on [0, min diag(T)], (d,e^2) via broadcast LDS.128.
__global__ __launch_bounds__(128, 7) void corr_eig_kernel(
    const float* __restrict__ sr, float* __restrict__ out, int M)
{
    __shared__ float  shG[WPB][32 * 20];    // 16 feats + pad (16B-aligned rows)
    __shared__ float  shV[WPB][2][32];      // double-buffered
    __shared__ float  shW[WPB][2][32];
    __shared__ float2 shDE[WPB][32];

    const int w    = threadIdx.x >> 5;
    const int lane = threadIdx.x & 31;
    const int mol  = blockIdx.x * WPB + w;
    if (mol >= M) return;

    float* G = shG[w];

    // ---------------- Phase 1: Gram ----------------
    float a[32];
    #pragma unroll
    for (int j = 0; j < 32; j++) a[j] = 0.f;

    // Own row: 128 floats = 32 x ulonglong2; chunk c covers feats [16c, 16c+16)
    const ulonglong2* g2 =
        reinterpret_cast<const ulonglong2*>(sr) + ((size_t)mol * 32 + lane) * 32;

    #pragma unroll 1
    for (int c = 0; c < 8; c++) {
        ulonglong2 xv[4];                      // own 16-feat chunk (16 regs)
        #pragma unroll
        for (int i = 0; i < 4; i++) xv[i] = g2[c * 4 + i];

        __syncwarp();                          // prior j-loop reads done
        #pragma unroll
        for (int i = 0; i < 4; i++)
            *reinterpret_cast<ulonglong2*>(&G[lane * 20 + 4 * i]) = xv[i];
        __syncwarp();

        #pragma unroll 4
        for (int j = 0; j < 32; j++) {
            unsigned long long acc = 0ull;     // two packed fp32 accumulators
            #pragma unroll
            for (int i = 0; i < 4; i++) {
                ulonglong2 y = *reinterpret_cast<const ulonglong2*>(&G[j * 20 + 4 * i]);
                FMA_F32X2(acc, xv[i].x, y.x, acc);
                FMA_F32X2(acc, xv[i].y, y.y, acc);
            }
            float s0, s1;
            asm("mov.b64 {%0,%1}, %2;" : "=f"(s0), "=f"(s1) : "l"(acc));
            a[j] += s0 + s1;
        }
    }

    // ---------------- Phase 2: Householder tridiagonalization ----------------
    // Lane i owns row i. Inactive lanes (lane <= k) have v = w = 0: their rows
    // freeze and never contaminate active lanes. sV/sW entries for j <= k are 0,
    // so aligned LDS.128 over-reads are harmless.
    float d_reg = 0.f, e_reg = 0.f;

    #pragma unroll
    for (int k = 0; k < 30; k++) {
        const bool act = (lane > k);

        // Trailing norm of OWN row, 4 independent chains (only lane k's used)
        float sc0 = 0.f, sc1 = 0.f, sc2 = 0.f, sc3 = 0.f;
        #pragma unroll
        for (int j = k + 1; j < 32; j++) {
            if ((j & 3) == 0)      sc0 = fmaf(a[j], a[j], sc0);
            else if ((j & 3) == 1) sc1 = fmaf(a[j], a[j], sc1);
            else if ((j & 3) == 2) sc2 = fmaf(a[j], a[j], sc2);
            else                   sc3 = fmaf(a[j], a[j], sc3);
        }
        float sig_loc = (sc0 + sc1) + (sc2 + sc3);
        float sigma = __shfl_sync(FULL, sig_loc, k);
        float x1    = __shfl_sync(FULL, a[k + 1], k);   // A[k][k+1]

        float alpha = -copysignf(sqrtf(sigma), x1);
        bool  ok    = (sigma > 1e-20f);
        float beta  = ok ? 1.0f / (sigma - alpha * x1) : 0.f;   // 2 / v^T v
        if (lane == k) { d_reg = a[k]; e_reg = ok ? alpha : x1; }

        float v = act ? a[k] : 0.f;
        if (lane == k + 1) v = ok ? (x1 - alpha) : 0.f;

        float* sV = shV[w][k & 1];
        float* sW = shW[w][k & 1];
        sV[lane] = v;
        __syncwarp();

        // p = beta * (A v): V via broadcast LDS.128, 4 FMA chains
        float pc0 = 0.f, pc1 = 0.f, pc2 = 0.f, pc3 = 0.f;
        #pragma unroll
        for (int jq = (k + 1) >> 2; jq < 8; jq++) {
            float4 v4 = *reinterpret_cast<const float4*>(&sV[4 * jq]);
            pc0 = fmaf(a[4 * jq + 0], v4.x, pc0);
            pc1 = fmaf(a[4 * jq + 1], v4.y, pc1);
            pc2 = fmaf(a[4 * jq + 2], v4.z, pc2);
            pc3 = fmaf(a[4 * jq + 3], v4.w, pc3);
        }
        float p = ((pc0 + pc1) + (pc2 + pc3));
        p = act ? p * beta : 0.f;

        float s  = warpSum(p * v);                     // p^T v
        float wv = p - (0.5f * beta * s) * v;          // 0 on inactive lanes

        sW[lane] = wv;
        __syncwarp();

        // A <- A - v w^T - w v^T
        #pragma unroll
        for (int jq = (k + 1) >> 2; jq < 8; jq++) {
            float4 v4 = *reinterpret_cast<const float4*>(&sV[4 * jq]);
            float4 w4 = *reinterpret_cast<const float4*>(&sW[4 * jq]);
            a[4 * jq + 0] -= v * w4.x + wv * v4.x;
            a[4 * jq + 1] -= v * w4.y + wv * v4.y;
            a[4 * jq + 2] -= v * w4.z + wv * v4.z;
            a[4 * jq + 3] -= v * w4.w + wv * v4.w;
        }
    }
    if (lane == 30) { d_reg = a[30]; e_reg = a[31]; }
    if (lane == 31) { d_reg = a[31]; e_reg = 0.f; }

    // ---------------- Phase 3: Sturm bisection ----------------
    // C is PSD => lambda_min in [0, min_i T_ii] (Rayleigh / interlacing).
    __syncwarp();
    shDE[w][lane] = make_float2(d_reg, e_reg * e_reg);
    __syncwarp();
    const float4* DE4 = reinterpret_cast<const float4*>(shDE[w]);  // (d,e2) pairs

    float lo = 0.f;
    float hi = warpMin(d_reg) * 1.0001f;

    #pragma unroll 1
    for (int r = 0; r < 4; r++) {
        float h = (hi - lo) * (1.0f / 33.0f);
        float x = fmaf(h, (float)(lane + 1), lo);

        float4 t = DE4[0];                       // d0, e2_0, d1, e2_1
        float q   = t.x - x;
        int   cnt = (q < 0.f);
        float eprev = t.y;
        {
            float qn = (t.z - x) - __fdividef(eprev, q);
            if (qn == 0.f) qn = -1e-30f;
            cnt += (qn < 0.f);
            q = qn; eprev = t.w;
        }
        #pragma unroll
        for (int m = 1; m < 16; m++) {
            t = DE4[m];
            float qn = (t.x - x) - __fdividef(eprev, q);
            if (qn == 0.f) qn = -1e-30f;
            cnt += (qn < 0.f);
            q = qn; eprev = t.y;

            qn = (t.z - x) - __fdividef(eprev, q);
            if (qn == 0.f) qn = -1e-30f;
            cnt += (qn < 0.f);
            q = qn; eprev = t.w;
        }

        unsigned mask = __ballot_sync(FULL, cnt >= 1);
        int j0 = mask ? (__ffs(mask) - 1) : 32;
        lo += h * (float)j0;
        hi  = lo + h;
    }

    if (lane == 0) out[mol] = 0.5f * (lo + hi);
}

extern "C" void kernel_launch(void* const* d_in, const int* in_sizes, int n_in,
                              void* d_out, int out_size) {
    const float* sr = (const float*)d_in[0];
    // d_in[1] (idx_m) unused: uniform groups -> [M, 32, 128]
    float* out = (float*)d_out;
    int M = in_sizes[0] >> 12;   // / (32*128)

    int blocks = (M + WPB - 1) / WPB;
    corr_eig_kernel<<<blocks, 128>>>(sr, out, M);
}